// round 15
// baseline (speedup 1.0000x reference)
#include <cuda_runtime.h>
#include <cuda_fp16.h>
#include <cstdint>

#define BT 192
#define NN 512
#define FF 64
#define ALPHA_F 0.2f

// ---------------- device scratch ----------------
__device__ __half g_Wh[(size_t)BT * NN * FF];    // [bt][node][o], fp16
__device__ float g_Wh1[BT * NN];
__device__ float g_Wh2[BT * NN];
__device__ uint32_t g_adjb[NN * 16];             // adj bitmask

// ---------------- helpers ----------------
__device__ __forceinline__ uint32_t smem_u32(const void* p) {
    uint32_t a;
    asm("{ .reg .u64 t; cvta.to.shared.u64 t, %1; cvt.u32.u64 %0, t; }" : "=r"(a) : "l"(p));
    return a;
}
__device__ __forceinline__ uint32_t h2u(__half2 v) { return *reinterpret_cast<uint32_t*>(&v); }
__device__ __forceinline__ __half2 u2h(uint32_t u) { return *reinterpret_cast<__half2*>(&u); }

__device__ __forceinline__ void mma16816(float* c, uint32_t a0, uint32_t a1, uint32_t a2,
                                         uint32_t a3, uint32_t b0, uint32_t b1) {
    asm volatile(
        "mma.sync.aligned.m16n8k16.row.col.f32.f16.f16.f32 "
        "{%0,%1,%2,%3}, {%4,%5,%6,%7}, {%8,%9}, {%0,%1,%2,%3};"
        : "+f"(c[0]), "+f"(c[1]), "+f"(c[2]), "+f"(c[3])
        : "r"(a0), "r"(a1), "r"(a2), "r"(a3), "r"(b0), "r"(b1));
}
__device__ __forceinline__ void ldsm4(uint32_t addr, uint32_t& r0, uint32_t& r1,
                                      uint32_t& r2, uint32_t& r3) {
    asm volatile("ldmatrix.sync.aligned.m8n8.x4.shared.b16 {%0,%1,%2,%3}, [%4];"
                 : "=r"(r0), "=r"(r1), "=r"(r2), "=r"(r3) : "r"(addr));
}
__device__ __forceinline__ void ldsm4t(uint32_t addr, uint32_t& r0, uint32_t& r1,
                                       uint32_t& r2, uint32_t& r3) {
    asm volatile("ldmatrix.sync.aligned.m8n8.x4.trans.shared.b16 {%0,%1,%2,%3}, [%4];"
                 : "=r"(r0), "=r"(r1), "=r"(r2), "=r"(r3) : "r"(addr));
}
__device__ __forceinline__ uint32_t hgt2_mask(uint32_t a, uint32_t b) {
    uint32_t m;
    asm("set.gt.u32.f16x2 %0, %1, %2;" : "=r"(m) : "r"(a), "r"(b));
    return m;
}

// ---------------------------------------------------------------------------
// Kernel 1: blocks [0,768): Wh = h @ W via split-fp16 mma (3 planes) ->
//           g_Wh [node][o] fp16; Wh1/Wh2 exact via h @ (W a1/2).
//           blocks [768,1280): adj -> bitmask.
// smem: A-hi 16KB @0, A-lo 16KB @16384, W-hi 8KB @32768, W-lo 8KB @40960,
//       a 512B @49152, w1vec/w2vec 512B @49664.
// ---------------------------------------------------------------------------
#define WH_SMEM 50176
__global__ __launch_bounds__(128) void wh_mma_kernel(const float* __restrict__ h,
                                                     const float* __restrict__ W,
                                                     const float* __restrict__ a,
                                                     const float* __restrict__ adj) {
    if (blockIdx.x >= 768) {
        int t = (blockIdx.x - 768) * 128 + threadIdx.x;     // float4 index
        float4 v = ((const float4*)adj)[t];
        unsigned nib = (v.x > 0.f ? 1u : 0u) | (v.y > 0.f ? 2u : 0u) |
                       (v.z > 0.f ? 4u : 0u) | (v.w > 0.f ? 8u : 0u);
        unsigned b = nib | (__shfl_down_sync(0xffffffffu, nib, 1) << 4);
        b = b | (__shfl_down_sync(0xffffffffu, b, 2) << 8);
        b = b | (__shfl_down_sync(0xffffffffu, b, 4) << 16);
        if ((threadIdx.x & 7) == 0) g_adjb[t >> 3] = b;
        return;
    }

    extern __shared__ char sm[];
    uint32_t sbase = smem_u32(sm);
    float* sa = (float*)(sm + 49152);
    float* sw = (float*)(sm + 49664);          // w1vec[64] then w2vec[64], indexed by f

    int tid = threadIdx.x;
    int wid = tid >> 5, lane = tid & 31;
    int bt = blockIdx.x >> 2;
    int nwin = (blockIdx.x & 3) * 128;

    // 1) stage W fp32 @0 and a
    {
        float4* d = (float4*)sm;
        const float4* s4 = (const float4*)W;
        #pragma unroll
        for (int i = 0; i < 8; i++) d[tid + i * 128] = s4[tid + i * 128];
        sa[tid] = a[tid];
    }
    __syncthreads();

    // 2a) transpose+split W -> Wt[o][f] hi/lo planes (swizzled)
    {
        const float* w32 = (const float*)sm;
        int o = tid >> 1, fh = (tid & 1) * 32;
        #pragma unroll
        for (int g = 0; g < 4; g++) {
            float v[8];
            #pragma unroll
            for (int j = 0; j < 8; j++) v[j] = w32[(fh + g * 8 + j) * 64 + o];
            uint32_t hw[4], lw[4];
            #pragma unroll
            for (int p = 0; p < 4; p++) {
                __half2 hh = __floats2half2_rn(v[2 * p], v[2 * p + 1]);
                hw[p] = h2u(hh);
                lw[p] = h2u(__floats2half2_rn(v[2 * p] - __low2float(hh),
                                              v[2 * p + 1] - __high2float(hh)));
            }
            uint32_t dst = (uint32_t)(o * 128 + ((fh * 2 + g * 16) ^ ((o & 7) << 4)));
            *(uint4*)(sm + 32768 + dst) = make_uint4(hw[0], hw[1], hw[2], hw[3]);
            *(uint4*)(sm + 40960 + dst) = make_uint4(lw[0], lw[1], lw[2], lw[3]);
        }
    }
    // 2b) w1vec[f] = sum_o W[f][o]*a1[o] ; w2vec[f] likewise with a2.
    //     (contraction over OUTPUT dim o; result indexed by input feature f)
    {
        const float* w32 = (const float*)sm;
        int f = tid & 63;
        const float* av = sa + (tid >> 6) * 64;
        float acc = 0.f;
        #pragma unroll 16
        for (int o = 0; o < 64; o++) acc += w32[f * 64 + o] * av[o];
        sw[(tid >> 6) * 64 + f] = acc;
    }
    __syncthreads();

    // 3) stage h row -> A hi/lo planes; fused exact Wh1/Wh2 dot products
    {
        int r = tid;
        int grow = bt * 512 + nwin + r;
        const float4* hr = (const float4*)(h + (size_t)grow * 64);
        float d1 = 0.f, d2 = 0.f;
        #pragma unroll
        for (int g = 0; g < 8; g++) {
            float4 x = hr[2 * g], y = hr[2 * g + 1];
            __half2 h0 = __floats2half2_rn(x.x, x.y), h1 = __floats2half2_rn(x.z, x.w);
            __half2 h2 = __floats2half2_rn(y.x, y.y), h3 = __floats2half2_rn(y.z, y.w);
            uint4 hi = make_uint4(h2u(h0), h2u(h1), h2u(h2), h2u(h3));
            uint4 lo = make_uint4(
                h2u(__floats2half2_rn(x.x - __low2float(h0), x.y - __high2float(h0))),
                h2u(__floats2half2_rn(x.z - __low2float(h1), x.w - __high2float(h1))),
                h2u(__floats2half2_rn(y.x - __low2float(h2), y.y - __high2float(h2))),
                h2u(__floats2half2_rn(y.z - __low2float(h3), y.w - __high2float(h3))));
            uint32_t dst = (uint32_t)(r * 128 + ((g * 16) ^ ((r & 7) << 4)));
            *(uint4*)(sm + dst) = hi;
            *(uint4*)(sm + 16384 + dst) = lo;
            int f = g * 8;
            d1 += x.x * sw[f] + x.y * sw[f + 1] + x.z * sw[f + 2] + x.w * sw[f + 3]
                + y.x * sw[f + 4] + y.y * sw[f + 5] + y.z * sw[f + 6] + y.w * sw[f + 7];
            d2 += x.x * sw[64 + f] + x.y * sw[64 + f + 1] + x.z * sw[64 + f + 2] + x.w * sw[64 + f + 3]
                + y.x * sw[64 + f + 4] + y.y * sw[64 + f + 5] + y.z * sw[64 + f + 6] + y.w * sw[64 + f + 7];
        }
        g_Wh1[grow] = d1;
        g_Wh2[grow] = d2;
    }
    __syncthreads();

    // 4) MMA: per warp 32 rows x 64 cols, k=64; planes hh + hl + lh
    float C[2][8][4];
    #pragma unroll
    for (int mt = 0; mt < 2; mt++)
        #pragma unroll
        for (int nt = 0; nt < 8; nt++)
            #pragma unroll
            for (int r = 0; r < 4; r++) C[mt][nt][r] = 0.f;

    int li = lane & 7, gidx = lane >> 3, nthalf = gidx >> 1, kh16 = (gidx & 1) << 4;
    uint32_t ro_a = (uint32_t)((wid * 32 + (lane & 15)) * 128);
    uint32_t xw_a = (uint32_t)((lane >> 4) * 16);
    uint32_t swz_a = (uint32_t)((lane & 7) << 4);
    uint32_t rowW[4];
    #pragma unroll
    for (int m = 0; m < 4; m++)
        rowW[m] = 32768u + (uint32_t)(((2 * m + nthalf) * 8 + li) * 128);

    #pragma unroll
    for (int s = 0; s < 4; s++) {
        uint32_t ac = (uint32_t)((s * 32 + xw_a) ^ swz_a);
        uint32_t Ah[2][4], Al[2][4];
        ldsm4(sbase + ro_a + ac, Ah[0][0], Ah[0][1], Ah[0][2], Ah[0][3]);
        ldsm4(sbase + ro_a + 2048 + ac, Ah[1][0], Ah[1][1], Ah[1][2], Ah[1][3]);
        ldsm4(sbase + 16384 + ro_a + ac, Al[0][0], Al[0][1], Al[0][2], Al[0][3]);
        ldsm4(sbase + 16384 + ro_a + 2048 + ac, Al[1][0], Al[1][1], Al[1][2], Al[1][3]);
        uint32_t wc = (uint32_t)(((s << 5) + kh16) ^ (li << 4));
        #pragma unroll
        for (int m = 0; m < 4; m++) {
            uint32_t bh0, bh1, bh2, bh3, bl0, bl1, bl2, bl3;
            ldsm4(sbase + rowW[m] + wc, bh0, bh1, bh2, bh3);
            ldsm4(sbase + rowW[m] + 8192 + wc, bl0, bl1, bl2, bl3);
            #pragma unroll
            for (int mt = 0; mt < 2; mt++) {
                mma16816(C[mt][2 * m], Ah[mt][0], Ah[mt][1], Ah[mt][2], Ah[mt][3], bh0, bh1);
                mma16816(C[mt][2 * m], Al[mt][0], Al[mt][1], Al[mt][2], Al[mt][3], bh0, bh1);
                mma16816(C[mt][2 * m], Ah[mt][0], Ah[mt][1], Ah[mt][2], Ah[mt][3], bl0, bl1);
                mma16816(C[mt][2 * m + 1], Ah[mt][0], Ah[mt][1], Ah[mt][2], Ah[mt][3], bh2, bh3);
                mma16816(C[mt][2 * m + 1], Al[mt][0], Al[mt][1], Al[mt][2], Al[mt][3], bh2, bh3);
                mma16816(C[mt][2 * m + 1], Ah[mt][0], Ah[mt][1], Ah[mt][2], Ah[mt][3], bl2, bl3);
            }
        }
    }

    // 5) epilogue: fp16 Wh [node][o]
    int tg = lane >> 2, q = lane & 3;
    #pragma unroll
    for (int mt = 0; mt < 2; mt++) {
        int rbase = bt * 512 + nwin + wid * 32 + mt * 16 + tg;
        #pragma unroll
        for (int nt = 0; nt < 8; nt++) {
            *(uint32_t*)(g_Wh + (size_t)rbase * 64 + nt * 8 + 2 * q) =
                h2u(__floats2half2_rn(C[mt][nt][0], C[mt][nt][1]));
            *(uint32_t*)(g_Wh + (size_t)(rbase + 8) * 64 + nt * 8 + 2 * q) =
                h2u(__floats2half2_rn(C[mt][nt][2], C[mt][nt][3]));
        }
    }
}

// ---------------------------------------------------------------------------
// Kernel 2: fused att, 16-row warp tiles for occupancy (3 CTAs/SM).
// Block = 256 thr (8 warps x 16 rows) = 128 rows; grid = BT*4.
// smem: B0 8KB @0, B1 8KB @8192, adj 8KB @16384, tbl 2KB @24576, whh 1KB @26624.
// ---------------------------------------------------------------------------
#define SM_B0 0
#define SM_B1 8192
#define SM_ADJ 16384
#define SM_TBL 24576
#define SM_WHH 26624
#define ATT_SMEM 27648

__global__ __launch_bounds__(256, 3) void att_mma_kernel(float* __restrict__ out) {
    extern __shared__ char smem[];
    uint32_t sbase = smem_u32(smem);
    uint2* tbl = (uint2*)(smem + SM_TBL);        // (e2p_h2, e2n_h2) per col pair
    uint32_t* whh = (uint32_t*)(smem + SM_WHH);  // wh2 half2 per col pair
    uint32_t* adjb = (uint32_t*)(smem + SM_ADJ);

    int tid = threadIdx.x;
    int w = tid >> 5, lane = tid & 31;
    int q = lane & 3, tg = lane >> 2;
    int bt = blockIdx.x >> 2;
    int i0 = (blockIdx.x & 3) << 7;              // 128-row tile

    // stage exp tables + adj bits (128 rows x 16 words = 8KB)
    {
        float w2a = g_Wh2[bt * 512 + 2 * tid];
        float w2b = g_Wh2[bt * 512 + 2 * tid + 1];
        tbl[tid] = make_uint2(h2u(__floats2half2_rn(__expf(w2a), __expf(w2b))),
                              h2u(__floats2half2_rn(__expf(ALPHA_F * w2a), __expf(ALPHA_F * w2b))));
        whh[tid] = h2u(__floats2half2_rn(w2a, w2b));
    }
    {
        const uint4* src = (const uint4*)(g_adjb + i0 * 16);
        uint4* dst = (uint4*)adjb;
        dst[tid] = src[tid];
        dst[tid + 256] = src[tid + 256];
    }

    // per-row constants (rows 16w+tg, 16w+tg+8)
    uint32_t unw1[2], uE1p[2], uE1n[2];
    #pragma unroll
    for (int ri = 0; ri < 2; ri++) {
        float w1 = g_Wh1[bt * 512 + i0 + 16 * w + tg + 8 * ri];
        unw1[ri] = h2u(__floats2half2_rn(-w1, -w1));
        float ep = __expf(w1), en = __expf(ALPHA_F * w1);
        uE1p[ri] = h2u(__floats2half2_rn(ep, ep));
        uE1n[ri] = h2u(__floats2half2_rn(en, en));
    }

    float C[8][4];
    #pragma unroll
    for (int nt = 0; nt < 8; nt++)
        #pragma unroll
        for (int r = 0; r < 4; r++) C[nt][r] = 0.f;
    float Cs[4] = {0.f, 0.f, 0.f, 0.f};
    uint32_t bone = (lane < 4) ? 0x3C003C00u : 0u;   // ones column n=0

    // trans-B addressing
    uint32_t ro = (uint32_t)((lane & 15) * 128);
    uint32_t cm[4];
    {
        uint32_t xw = (uint32_t)((lane >> 4) * 16);
        uint32_t swz = (uint32_t)((lane & 7) << 4);
        #pragma unroll
        for (int m = 0; m < 4; m++) cm[m] = (m * 32 + xw) ^ swz;
    }

    // B staging: chunk = 64 node-rows x 128B, double-buffered
    const uint4* srcW = (const uint4*)(g_Wh + (size_t)bt * 512 * 64);
    int n0 = tid >> 3, g0 = tid & 7;
    int n1 = (tid + 256) >> 3;
    uint32_t db0 = (uint32_t)(n0 * 128 + ((g0 * 16) ^ ((n0 & 7) << 4)));
    uint32_t db1 = (uint32_t)(n1 * 128 + ((g0 * 16) ^ ((n1 & 7) << 4)));
    uint4 pre0 = srcW[tid], pre1 = srcW[tid + 256];
    *(uint4*)(smem + SM_B0 + db0) = pre0;
    *(uint4*)(smem + SM_B0 + db1) = pre1;
    __syncthreads();

    for (int c = 0; c < 8; c++) {
        if (c < 7) {
            pre0 = srcW[(c + 1) * 512 + tid];
            pre1 = srcW[(c + 1) * 512 + tid + 256];
        }
        uint32_t bufb = sbase + ((c & 1) ? SM_B1 : SM_B0);

        uint32_t rx[2], ry[2];
        #pragma unroll
        for (int ri = 0; ri < 2; ri++) {
            uint2 wv = *(const uint2*)&adjb[(16 * w + tg + 8 * ri) * 16 + 2 * c];
            rx[ri] = wv.x >> (2 * q);
            ry[ri] = wv.y >> (2 * q);
        }

        #pragma unroll
        for (int s = 0; s < 4; s++) {
            int idx = c * 32 + s * 8 + q;
            uint2 eA = tbl[idx], eB = tbl[idx + 4];
            uint32_t whA = whh[idx], whB = whh[idx + 4];

            uint32_t ah[4];
            #pragma unroll
            for (int ri = 0; ri < 2; ri++) {
                uint32_t u = (s == 0) ? rx[ri] : (s == 1) ? (rx[ri] >> 16)
                           : (s == 2) ? ry[ri] : (ry[ri] >> 16);
                uint32_t uB = u >> 8;
                uint32_t mA = hgt2_mask(whA, unw1[ri]);
                uint32_t mB = hgt2_mask(whB, unw1[ri]);
                uint32_t e2A = (eA.x & mA) | (eA.y & ~mA);
                uint32_t E1A = (uE1p[ri] & mA) | (uE1n[ri] & ~mA);
                uint32_t e2B = (eB.x & mB) | (eB.y & ~mB);
                uint32_t E1B = (uE1p[ri] & mB) | (uE1n[ri] & ~mB);
                uint32_t vA = h2u(__hmul2(u2h(e2A), u2h(E1A)));
                uint32_t vB = h2u(__hmul2(u2h(e2B), u2h(E1B)));
                uint32_t amA = (u & 1u) * 0xFFFFu | (u & 2u) * 0x7FFF8000u;
                uint32_t amB = (uB & 1u) * 0xFFFFu | (uB & 2u) * 0x7FFF8000u;
                ah[ri] = vA & amA;
                ah[ri + 2] = vB & amB;
            }

            uint32_t rbase = bufb + (uint32_t)(s * 2048) + ro;
            #pragma unroll
            for (int m = 0; m < 4; m++) {
                uint32_t b0, b1, b2, b3;
                ldsm4t(rbase + cm[m], b0, b1, b2, b3);
                mma16816(C[2 * m], ah[0], ah[1], ah[2], ah[3], b0, b1);
                mma16816(C[2 * m + 1], ah[0], ah[1], ah[2], ah[3], b2, b3);
            }
            mma16816(Cs, ah[0], ah[1], ah[2], ah[3], bone, bone);
        }

        if (c < 7) {
            char* nbuf = smem + (((c + 1) & 1) ? SM_B1 : SM_B0);
            *(uint4*)(nbuf + db0) = pre0;
            *(uint4*)(nbuf + db1) = pre1;
            __syncthreads();
        }
    }

    // epilogue: row sums in ones-column (col 0, q==0 lanes)
    float s0 = __shfl_sync(0xffffffffu, Cs[0], lane & 28);
    float s1 = __shfl_sync(0xffffffffu, Cs[2], lane & 28);
    float inv0 = 1.f / s0, inv1 = 1.f / s1;
    int row0 = bt * 512 + i0 + 16 * w + tg;
    float* o0 = out + (size_t)row0 * 64 + 2 * q;
    float* o1 = o0 + 8 * 64;
    #pragma unroll
    for (int nt = 0; nt < 8; nt++) {
        float v0 = C[nt][0] * inv0, v1 = C[nt][1] * inv0;
        float v2 = C[nt][2] * inv1, v3 = C[nt][3] * inv1;
        v0 = v0 > 0.f ? v0 : __expf(v0) - 1.f;
        v1 = v1 > 0.f ? v1 : __expf(v1) - 1.f;
        v2 = v2 > 0.f ? v2 : __expf(v2) - 1.f;
        v3 = v3 > 0.f ? v3 : __expf(v3) - 1.f;
        *(float2*)&o0[nt * 8] = make_float2(v0, v1);
        *(float2*)&o1[nt * 8] = make_float2(v2, v3);
    }
}

// ---------------------------------------------------------------------------
extern "C" void kernel_launch(void* const* d_in, const int* in_sizes, int n_in,
                              void* d_out, int out_size) {
    const float* h   = (const float*)d_in[0];
    const float* adj = (const float*)d_in[1];
    const float* W   = (const float*)d_in[2];
    const float* a   = (const float*)d_in[3];
    float* out = (float*)d_out;

    cudaFuncSetAttribute(wh_mma_kernel, cudaFuncAttributeMaxDynamicSharedMemorySize,
                         WH_SMEM);
    cudaFuncSetAttribute(att_mma_kernel, cudaFuncAttributeMaxDynamicSharedMemorySize,
                         ATT_SMEM);

    wh_mma_kernel<<<768 + 512, 128, WH_SMEM>>>(h, W, a, adj);
    att_mma_kernel<<<BT * 4, 256, ATT_SMEM>>>(out);
}

// round 17
// speedup vs baseline: 1.0582x; 1.0582x over previous
#include <cuda_runtime.h>
#include <cuda_fp16.h>
#include <cstdint>

#define BT 192
#define NN 512
#define FF 64
#define ALPHA_F 0.2f

// ---------------- device scratch ----------------
__device__ __half g_Wh[(size_t)BT * NN * FF];    // [bt][node][o], fp16
__device__ float g_Wh1[BT * NN];
__device__ float g_Wh2[BT * NN];
__device__ uint32_t g_adjb[NN * 16];             // adj bitmask

// ---------------- helpers ----------------
__device__ __forceinline__ uint32_t smem_u32(const void* p) {
    uint32_t a;
    asm("{ .reg .u64 t; cvta.to.shared.u64 t, %1; cvt.u32.u64 %0, t; }" : "=r"(a) : "l"(p));
    return a;
}
__device__ __forceinline__ uint32_t h2u(__half2 v) { return *reinterpret_cast<uint32_t*>(&v); }
__device__ __forceinline__ __half2 u2h(uint32_t u) { return *reinterpret_cast<__half2*>(&u); }

__device__ __forceinline__ void mma16816(float* c, uint32_t a0, uint32_t a1, uint32_t a2,
                                         uint32_t a3, uint32_t b0, uint32_t b1) {
    asm volatile(
        "mma.sync.aligned.m16n8k16.row.col.f32.f16.f16.f32 "
        "{%0,%1,%2,%3}, {%4,%5,%6,%7}, {%8,%9}, {%0,%1,%2,%3};"
        : "+f"(c[0]), "+f"(c[1]), "+f"(c[2]), "+f"(c[3])
        : "r"(a0), "r"(a1), "r"(a2), "r"(a3), "r"(b0), "r"(b1));
}
__device__ __forceinline__ void ldsm4(uint32_t addr, uint32_t& r0, uint32_t& r1,
                                      uint32_t& r2, uint32_t& r3) {
    asm volatile("ldmatrix.sync.aligned.m8n8.x4.shared.b16 {%0,%1,%2,%3}, [%4];"
                 : "=r"(r0), "=r"(r1), "=r"(r2), "=r"(r3) : "r"(addr));
}
__device__ __forceinline__ void ldsm4t(uint32_t addr, uint32_t& r0, uint32_t& r1,
                                       uint32_t& r2, uint32_t& r3) {
    asm volatile("ldmatrix.sync.aligned.m8n8.x4.trans.shared.b16 {%0,%1,%2,%3}, [%4];"
                 : "=r"(r0), "=r"(r1), "=r"(r2), "=r"(r3) : "r"(addr));
}
__device__ __forceinline__ uint32_t hgt2_mask(uint32_t a, uint32_t b) {
    uint32_t m;
    asm("set.gt.u32.f16x2 %0, %1, %2;" : "=r"(m) : "r"(a), "r"(b));
    return m;
}

// ---------------------------------------------------------------------------
// Kernel 1: blocks [0,768): Wh = h @ W via split-fp16 mma (3 planes) ->
//           g_Wh [node][o] fp16; Wh1/Wh2 exact via h @ (W a1/2).
//           blocks [768,1280): adj -> bitmask.
// smem: A-hi 16KB @0, A-lo 16KB @16384, W-hi 8KB @32768, W-lo 8KB @40960,
//       a 512B @49152, w1vec/w2vec 512B @49664.
// ---------------------------------------------------------------------------
#define WH_SMEM 50176
__global__ __launch_bounds__(128) void wh_mma_kernel(const float* __restrict__ h,
                                                     const float* __restrict__ W,
                                                     const float* __restrict__ a,
                                                     const float* __restrict__ adj) {
    if (blockIdx.x >= 768) {
        int t = (blockIdx.x - 768) * 128 + threadIdx.x;     // float4 index
        float4 v = ((const float4*)adj)[t];
        unsigned nib = (v.x > 0.f ? 1u : 0u) | (v.y > 0.f ? 2u : 0u) |
                       (v.z > 0.f ? 4u : 0u) | (v.w > 0.f ? 8u : 0u);
        unsigned b = nib | (__shfl_down_sync(0xffffffffu, nib, 1) << 4);
        b = b | (__shfl_down_sync(0xffffffffu, b, 2) << 8);
        b = b | (__shfl_down_sync(0xffffffffu, b, 4) << 16);
        if ((threadIdx.x & 7) == 0) g_adjb[t >> 3] = b;
        return;
    }

    extern __shared__ char sm[];
    uint32_t sbase = smem_u32(sm);
    float* sa = (float*)(sm + 49152);
    float* sw = (float*)(sm + 49664);          // w1vec[64] then w2vec[64], indexed by f

    int tid = threadIdx.x;
    int wid = tid >> 5, lane = tid & 31;
    int bt = blockIdx.x >> 2;
    int nwin = (blockIdx.x & 3) * 128;

    // 1) stage W fp32 @0 and a
    {
        float4* d = (float4*)sm;
        const float4* s4 = (const float4*)W;
        #pragma unroll
        for (int i = 0; i < 8; i++) d[tid + i * 128] = s4[tid + i * 128];
        sa[tid] = a[tid];
    }
    __syncthreads();

    // 2a) transpose+split W -> Wt[o][f] hi/lo planes (swizzled)
    {
        const float* w32 = (const float*)sm;
        int o = tid >> 1, fh = (tid & 1) * 32;
        #pragma unroll
        for (int g = 0; g < 4; g++) {
            float v[8];
            #pragma unroll
            for (int j = 0; j < 8; j++) v[j] = w32[(fh + g * 8 + j) * 64 + o];
            uint32_t hw[4], lw[4];
            #pragma unroll
            for (int p = 0; p < 4; p++) {
                __half2 hh = __floats2half2_rn(v[2 * p], v[2 * p + 1]);
                hw[p] = h2u(hh);
                lw[p] = h2u(__floats2half2_rn(v[2 * p] - __low2float(hh),
                                              v[2 * p + 1] - __high2float(hh)));
            }
            uint32_t dst = (uint32_t)(o * 128 + ((fh * 2 + g * 16) ^ ((o & 7) << 4)));
            *(uint4*)(sm + 32768 + dst) = make_uint4(hw[0], hw[1], hw[2], hw[3]);
            *(uint4*)(sm + 40960 + dst) = make_uint4(lw[0], lw[1], lw[2], lw[3]);
        }
    }
    // 2b) w1vec[f] = sum_o W[f][o]*a1[o] ; w2vec[f] likewise with a2.
    //     Diagonal skew o = (j+f)&63 -> bank (j+f)%32: conflict-free across lanes.
    {
        const float* w32 = (const float*)sm;
        int f = tid & 63;
        const float* av = sa + (tid >> 6) * 64;
        float acc = 0.f;
        #pragma unroll 16
        for (int j = 0; j < 64; j++) {
            int o = (j + f) & 63;
            acc += w32[f * 64 + o] * av[o];
        }
        sw[(tid >> 6) * 64 + f] = acc;
    }
    __syncthreads();

    // 3) stage h row -> A hi/lo planes; fused exact Wh1/Wh2 dot products
    {
        int r = tid;
        int grow = bt * 512 + nwin + r;
        const float4* hr = (const float4*)(h + (size_t)grow * 64);
        float d1 = 0.f, d2 = 0.f;
        #pragma unroll
        for (int g = 0; g < 8; g++) {
            float4 x = hr[2 * g], y = hr[2 * g + 1];
            __half2 h0 = __floats2half2_rn(x.x, x.y), h1 = __floats2half2_rn(x.z, x.w);
            __half2 h2 = __floats2half2_rn(y.x, y.y), h3 = __floats2half2_rn(y.z, y.w);
            uint4 hi = make_uint4(h2u(h0), h2u(h1), h2u(h2), h2u(h3));
            uint4 lo = make_uint4(
                h2u(__floats2half2_rn(x.x - __low2float(h0), x.y - __high2float(h0))),
                h2u(__floats2half2_rn(x.z - __low2float(h1), x.w - __high2float(h1))),
                h2u(__floats2half2_rn(y.x - __low2float(h2), y.y - __high2float(h2))),
                h2u(__floats2half2_rn(y.z - __low2float(h3), y.w - __high2float(h3))));
            uint32_t dst = (uint32_t)(r * 128 + ((g * 16) ^ ((r & 7) << 4)));
            *(uint4*)(sm + dst) = hi;
            *(uint4*)(sm + 16384 + dst) = lo;
            int f = g * 8;
            d1 += x.x * sw[f] + x.y * sw[f + 1] + x.z * sw[f + 2] + x.w * sw[f + 3]
                + y.x * sw[f + 4] + y.y * sw[f + 5] + y.z * sw[f + 6] + y.w * sw[f + 7];
            d2 += x.x * sw[64 + f] + x.y * sw[64 + f + 1] + x.z * sw[64 + f + 2] + x.w * sw[64 + f + 3]
                + y.x * sw[64 + f + 4] + y.y * sw[64 + f + 5] + y.z * sw[64 + f + 6] + y.w * sw[64 + f + 7];
        }
        g_Wh1[grow] = d1;
        g_Wh2[grow] = d2;
    }
    __syncthreads();

    // 4) MMA: per warp 32 rows x 64 cols, k=64; planes hh + hl + lh
    float C[2][8][4];
    #pragma unroll
    for (int mt = 0; mt < 2; mt++)
        #pragma unroll
        for (int nt = 0; nt < 8; nt++)
            #pragma unroll
            for (int r = 0; r < 4; r++) C[mt][nt][r] = 0.f;

    int li = lane & 7, gidx = lane >> 3, nthalf = gidx >> 1, kh16 = (gidx & 1) << 4;
    uint32_t ro_a = (uint32_t)((wid * 32 + (lane & 15)) * 128);
    uint32_t xw_a = (uint32_t)((lane >> 4) * 16);
    uint32_t swz_a = (uint32_t)((lane & 7) << 4);
    uint32_t rowW[4];
    #pragma unroll
    for (int m = 0; m < 4; m++)
        rowW[m] = 32768u + (uint32_t)(((2 * m + nthalf) * 8 + li) * 128);

    #pragma unroll
    for (int s = 0; s < 4; s++) {
        uint32_t ac = (uint32_t)((s * 32 + xw_a) ^ swz_a);
        uint32_t Ah[2][4], Al[2][4];
        ldsm4(sbase + ro_a + ac, Ah[0][0], Ah[0][1], Ah[0][2], Ah[0][3]);
        ldsm4(sbase + ro_a + 2048 + ac, Ah[1][0], Ah[1][1], Ah[1][2], Ah[1][3]);
        ldsm4(sbase + 16384 + ro_a + ac, Al[0][0], Al[0][1], Al[0][2], Al[0][3]);
        ldsm4(sbase + 16384 + ro_a + 2048 + ac, Al[1][0], Al[1][1], Al[1][2], Al[1][3]);
        uint32_t wc = (uint32_t)(((s << 5) + kh16) ^ (li << 4));
        #pragma unroll
        for (int m = 0; m < 4; m++) {
            uint32_t bh0, bh1, bh2, bh3, bl0, bl1, bl2, bl3;
            ldsm4(sbase + rowW[m] + wc, bh0, bh1, bh2, bh3);
            ldsm4(sbase + rowW[m] + 8192 + wc, bl0, bl1, bl2, bl3);
            #pragma unroll
            for (int mt = 0; mt < 2; mt++) {
                mma16816(C[mt][2 * m], Ah[mt][0], Ah[mt][1], Ah[mt][2], Ah[mt][3], bh0, bh1);
                mma16816(C[mt][2 * m], Al[mt][0], Al[mt][1], Al[mt][2], Al[mt][3], bh0, bh1);
                mma16816(C[mt][2 * m], Ah[mt][0], Ah[mt][1], Ah[mt][2], Ah[mt][3], bl0, bl1);
                mma16816(C[mt][2 * m + 1], Ah[mt][0], Ah[mt][1], Ah[mt][2], Ah[mt][3], bh2, bh3);
                mma16816(C[mt][2 * m + 1], Al[mt][0], Al[mt][1], Al[mt][2], Al[mt][3], bh2, bh3);
                mma16816(C[mt][2 * m + 1], Ah[mt][0], Ah[mt][1], Ah[mt][2], Ah[mt][3], bl2, bl3);
            }
        }
    }

    // 5) epilogue: fp16 Wh [node][o]
    int tg = lane >> 2, q = lane & 3;
    #pragma unroll
    for (int mt = 0; mt < 2; mt++) {
        int rbase = bt * 512 + nwin + wid * 32 + mt * 16 + tg;
        #pragma unroll
        for (int nt = 0; nt < 8; nt++) {
            *(uint32_t*)(g_Wh + (size_t)rbase * 64 + nt * 8 + 2 * q) =
                h2u(__floats2half2_rn(C[mt][nt][0], C[mt][nt][1]));
            *(uint32_t*)(g_Wh + (size_t)(rbase + 8) * 64 + nt * 8 + 2 * q) =
                h2u(__floats2half2_rn(C[mt][nt][2], C[mt][nt][3]));
        }
    }
}

// ---------------------------------------------------------------------------
// Kernel 2: fused att, 16-row warp tiles for occupancy (3 CTAs/SM).
// Block = 256 thr (8 warps x 16 rows) = 128 rows; grid = BT*4.
// smem: B0 8KB @0, B1 8KB @8192, adj 8KB @16384, tbl 2KB @24576, whh 1KB @26624.
// ---------------------------------------------------------------------------
#define SM_B0 0
#define SM_B1 8192
#define SM_ADJ 16384
#define SM_TBL 24576
#define SM_WHH 26624
#define ATT_SMEM 27648

__global__ __launch_bounds__(256, 3) void att_mma_kernel(float* __restrict__ out) {
    extern __shared__ char smem[];
    uint32_t sbase = smem_u32(smem);
    uint2* tbl = (uint2*)(smem + SM_TBL);        // (e2p_h2, e2n_h2) per col pair
    uint32_t* whh = (uint32_t*)(smem + SM_WHH);  // wh2 half2 per col pair
    uint32_t* adjb = (uint32_t*)(smem + SM_ADJ);

    int tid = threadIdx.x;
    int w = tid >> 5, lane = tid & 31;
    int q = lane & 3, tg = lane >> 2;
    int bt = blockIdx.x >> 2;
    int i0 = (blockIdx.x & 3) << 7;              // 128-row tile

    // stage exp tables + adj bits (128 rows x 16 words = 8KB)
    {
        float w2a = g_Wh2[bt * 512 + 2 * tid];
        float w2b = g_Wh2[bt * 512 + 2 * tid + 1];
        tbl[tid] = make_uint2(h2u(__floats2half2_rn(__expf(w2a), __expf(w2b))),
                              h2u(__floats2half2_rn(__expf(ALPHA_F * w2a), __expf(ALPHA_F * w2b))));
        whh[tid] = h2u(__floats2half2_rn(w2a, w2b));
    }
    {
        const uint4* src = (const uint4*)(g_adjb + i0 * 16);
        uint4* dst = (uint4*)adjb;
        dst[tid] = src[tid];
        dst[tid + 256] = src[tid + 256];
    }

    // per-row constants (rows 16w+tg, 16w+tg+8)
    uint32_t unw1[2], uE1p[2], uE1n[2];
    #pragma unroll
    for (int ri = 0; ri < 2; ri++) {
        float w1 = g_Wh1[bt * 512 + i0 + 16 * w + tg + 8 * ri];
        unw1[ri] = h2u(__floats2half2_rn(-w1, -w1));
        float ep = __expf(w1), en = __expf(ALPHA_F * w1);
        uE1p[ri] = h2u(__floats2half2_rn(ep, ep));
        uE1n[ri] = h2u(__floats2half2_rn(en, en));
    }

    float C[8][4];
    #pragma unroll
    for (int nt = 0; nt < 8; nt++)
        #pragma unroll
        for (int r = 0; r < 4; r++) C[nt][r] = 0.f;
    float Cs[4] = {0.f, 0.f, 0.f, 0.f};
    uint32_t bone = (lane < 4) ? 0x3C003C00u : 0u;   // ones column n=0

    // trans-B addressing
    uint32_t ro = (uint32_t)((lane & 15) * 128);
    uint32_t cm[4];
    {
        uint32_t xw = (uint32_t)((lane >> 4) * 16);
        uint32_t swz = (uint32_t)((lane & 7) << 4);
        #pragma unroll
        for (int m = 0; m < 4; m++) cm[m] = (m * 32 + xw) ^ swz;
    }

    // B staging: chunk = 64 node-rows x 128B, double-buffered
    const uint4* srcW = (const uint4*)(g_Wh + (size_t)bt * 512 * 64);
    int n0 = tid >> 3, g0 = tid & 7;
    int n1 = (tid + 256) >> 3;
    uint32_t db0 = (uint32_t)(n0 * 128 + ((g0 * 16) ^ ((n0 & 7) << 4)));
    uint32_t db1 = (uint32_t)(n1 * 128 + ((g0 * 16) ^ ((n1 & 7) << 4)));
    uint4 pre0 = srcW[tid], pre1 = srcW[tid + 256];
    *(uint4*)(smem + SM_B0 + db0) = pre0;
    *(uint4*)(smem + SM_B0 + db1) = pre1;
    __syncthreads();

    for (int c = 0; c < 8; c++) {
        if (c < 7) {
            pre0 = srcW[(c + 1) * 512 + tid];
            pre1 = srcW[(c + 1) * 512 + tid + 256];
        }
        uint32_t bufb = sbase + ((c & 1) ? SM_B1 : SM_B0);

        uint32_t rx[2], ry[2];
        #pragma unroll
        for (int ri = 0; ri < 2; ri++) {
            uint2 wv = *(const uint2*)&adjb[(16 * w + tg + 8 * ri) * 16 + 2 * c];
            rx[ri] = wv.x >> (2 * q);
            ry[ri] = wv.y >> (2 * q);
        }

        #pragma unroll
        for (int s = 0; s < 4; s++) {
            int idx = c * 32 + s * 8 + q;
            uint2 eA = tbl[idx], eB = tbl[idx + 4];
            uint32_t whA = whh[idx], whB = whh[idx + 4];

            uint32_t ah[4];
            #pragma unroll
            for (int ri = 0; ri < 2; ri++) {
                uint32_t u = (s == 0) ? rx[ri] : (s == 1) ? (rx[ri] >> 16)
                           : (s == 2) ? ry[ri] : (ry[ri] >> 16);
                uint32_t uB = u >> 8;
                uint32_t mA = hgt2_mask(whA, unw1[ri]);
                uint32_t mB = hgt2_mask(whB, unw1[ri]);
                uint32_t e2A = (eA.x & mA) | (eA.y & ~mA);
                uint32_t E1A = (uE1p[ri] & mA) | (uE1n[ri] & ~mA);
                uint32_t e2B = (eB.x & mB) | (eB.y & ~mB);
                uint32_t E1B = (uE1p[ri] & mB) | (uE1n[ri] & ~mB);
                uint32_t vA = h2u(__hmul2(u2h(e2A), u2h(E1A)));
                uint32_t vB = h2u(__hmul2(u2h(e2B), u2h(E1B)));
                uint32_t amA = (u & 1u) * 0xFFFFu | (u & 2u) * 0x7FFF8000u;
                uint32_t amB = (uB & 1u) * 0xFFFFu | (uB & 2u) * 0x7FFF8000u;
                ah[ri] = vA & amA;
                ah[ri + 2] = vB & amB;
            }

            uint32_t rbase = bufb + (uint32_t)(s * 2048) + ro;
            #pragma unroll
            for (int m = 0; m < 4; m++) {
                uint32_t b0, b1, b2, b3;
                ldsm4t(rbase + cm[m], b0, b1, b2, b3);
                mma16816(C[2 * m], ah[0], ah[1], ah[2], ah[3], b0, b1);
                mma16816(C[2 * m + 1], ah[0], ah[1], ah[2], ah[3], b2, b3);
            }
            mma16816(Cs, ah[0], ah[1], ah[2], ah[3], bone, bone);
        }

        if (c < 7) {
            char* nbuf = smem + (((c + 1) & 1) ? SM_B1 : SM_B0);
            *(uint4*)(nbuf + db0) = pre0;
            *(uint4*)(nbuf + db1) = pre1;
            __syncthreads();
        }
    }

    // epilogue: row sums in ones-column (col 0, q==0 lanes)
    float s0 = __shfl_sync(0xffffffffu, Cs[0], lane & 28);
    float s1 = __shfl_sync(0xffffffffu, Cs[2], lane & 28);
    float inv0 = 1.f / s0, inv1 = 1.f / s1;
    int row0 = bt * 512 + i0 + 16 * w + tg;
    float* o0 = out + (size_t)row0 * 64 + 2 * q;
    float* o1 = o0 + 8 * 64;
    #pragma unroll
    for (int nt = 0; nt < 8; nt++) {
        float v0 = C[nt][0] * inv0, v1 = C[nt][1] * inv0;
        float v2 = C[nt][2] * inv1, v3 = C[nt][3] * inv1;
        v0 = v0 > 0.f ? v0 : __expf(v0) - 1.f;
        v1 = v1 > 0.f ? v1 : __expf(v1) - 1.f;
        v2 = v2 > 0.f ? v2 : __expf(v2) - 1.f;
        v3 = v3 > 0.f ? v3 : __expf(v3) - 1.f;
        *(float2*)&o0[nt * 8] = make_float2(v0, v1);
        *(float2*)&o1[nt * 8] = make_float2(v2, v3);
    }
}

// ---------------------------------------------------------------------------
extern "C" void kernel_launch(void* const* d_in, const int* in_sizes, int n_in,
                              void* d_out, int out_size) {
    const float* h   = (const float*)d_in[0];
    const float* adj = (const float*)d_in[1];
    const float* W   = (const float*)d_in[2];
    const float* a   = (const float*)d_in[3];
    float* out = (float*)d_out;

    cudaFuncSetAttribute(wh_mma_kernel, cudaFuncAttributeMaxDynamicSharedMemorySize,
                         WH_SMEM);
    cudaFuncSetAttribute(att_mma_kernel, cudaFuncAttributeMaxDynamicSharedMemorySize,
                         ATT_SMEM);

    wh_mma_kernel<<<768 + 512, 128, WH_SMEM>>>(h, W, a, adj);
    att_mma_kernel<<<BT * 4, 256, ATT_SMEM>>>(out);
}